// round 15
// baseline (speedup 1.0000x reference)
#include <cuda_runtime.h>
#include <math.h>

#define BB 65536
#define HH 256
#define EE 64
#define DD 2
#define PP 12
#define G4 1024
#define KTOT 320
#define TM 64            // rows per CTA
#define NT 512           // 16 warps: 2 warp-sets x 8 row-groups, 8 rows/warp
#define KT 16            // gate k-tile
#define KTH 64           // head k-tile
#define NGT 40           // gate tiles: 2 passes x 20
#define NTILES 44        // + 4 head tiles
#define TILE_FLOATS 8192
#define SMEM_FLOATS 55432

typedef unsigned long long u64;

// -------- scratch (allocation-free: __device__ globals) --------
__device__ float g_Wt2[NGT * TILE_FLOATS];     // gate weights, tile-ordered
__device__ float g_WheadT[HH * 128];           // [k][0..63]=W_sp1^T, [64..127]=W_un1^T
__device__ float g_c[(size_t)BB * HH];         // c-state scratch (64 MB)

// tile t<40: t=(p*20+ti); row k in [0,16); col = ws*256 + g*64 + jj
// maps to weight row j = g*256 + (ws*2+p)*64 + jj, K index kk = ti*16+k
__global__ void prep_kernel(const float* __restrict__ W_ih,
                            const float* __restrict__ W_hh,
                            const float* __restrict__ W_sp1,
                            const float* __restrict__ W_un1) {
    int idx = blockIdx.x * blockDim.x + threadIdx.x;
    const int gate_total = NGT * TILE_FLOATS;
    if (idx < gate_total) {
        int col  = idx & 511;
        int rest = idx >> 9;
        int k    = rest & 15;
        int tile = rest >> 4;           // 0..39
        int p = tile / 20, ti = tile % 20;
        int ws = col >> 8;
        int within = col & 255;
        int g  = within >> 6;
        int jj = within & 63;
        int kk = ti * KT + k;
        int jrow = g * 256 + (ws * 2 + p) * 64 + jj;
        g_Wt2[idx] = (kk < EE) ? W_ih[jrow * EE + kk] : W_hh[jrow * HH + (kk - EE)];
    } else {
        int r = idx - gate_total;
        if (r < HH * 128) {
            int k = r >> 7, o = r & 127;
            g_WheadT[r] = (o < 64) ? W_sp1[o * HH + k] : W_un1[(o - 64) * HH + k];
        }
    }
}

__device__ __forceinline__ float sigf(float x) { return 1.f / (1.f + expf(-x)); }
__device__ __forceinline__ float softplusf(float x) {
    return fmaxf(x, 0.f) + log1pf(expf(-fabsf(x)));
}
__device__ __forceinline__ u64 pack2(float lo, float hi) {
    u64 r;
    asm("mov.b64 %0, {%1, %2};" : "=l"(r)
        : "r"(__float_as_uint(lo)), "r"(__float_as_uint(hi)));
    return r;
}
__device__ __forceinline__ void unpack2(u64 v, float& lo, float& hi) {
    unsigned int a, b;
    asm("mov.b64 {%0, %1}, %2;" : "=r"(a), "=r"(b) : "l"(v));
    lo = __uint_as_float(a); hi = __uint_as_float(b);
}
#define FMA2(d, a, b) asm("fma.rn.f32x2 %0, %1, %2, %0;" : "+l"(d) : "l"(a), "l"(b))

// -------- main persistent-state kernel --------
__global__ void __launch_bounds__(NT, 1)
lstm_kernel(const float* __restrict__ enc_h, const float* __restrict__ enc_c,
            const float* __restrict__ last_pos,
            const float* __restrict__ W_embed, const float* __restrict__ b_embed,
            const float* __restrict__ b_ih, const float* __restrict__ b_hh,
            const float* __restrict__ W_pos, const float* __restrict__ b_pos,
            const float* __restrict__ b_sp1, const float* __restrict__ W_sp2,
            const float* __restrict__ b_sp2,
            const float* __restrict__ b_un1, const float* __restrict__ W_un2,
            const float* __restrict__ b_un2,
            float* __restrict__ out)
{
    extern __shared__ float sm[];
    float* hs0   = sm;                    // 16384
    float* hs1   = hs0 + TM * HH;         // 16384
    float* embs  = hs1 + TM * HH;         // 4096
    float* wtb   = embs + TM * EE;        // 2 x 8192
    float* bg    = wtb + 2 * TILE_FLOATS; // 1024
    float* wposI = bg + G4;               // 512: [k][2] interleaved
    float* s_bsp1 = wposI + 512;          // 64
    float* s_bun1 = s_bsp1 + 64;          // 64
    float* s_wsp2 = s_bun1 + 64;          // 64
    float* s_wun2 = s_wsp2 + 64;          // 128
    float* s_wemb = s_wun2 + 128;         // 128
    float* s_bemb = s_wemb + 128;         // 64
    float* s_misc = s_bemb + 64;          // 8
    float* ps     = s_misc + 8;           // 128   total 55432

    const int tid  = threadIdx.x;
    const int lane = tid & 31;
    const int w    = tid >> 5;            // 0..15
    const int ws   = w >> 3;              // warp-set 0/1 (j-split)
    const int wg   = w & 7;               // row-group
    const int myrow = wg * 8;             // warp owns 8 rows
    const int row0 = blockIdx.x * TM;

    // ---- init ----
    for (int i = tid; i < TM * HH; i += NT) hs0[i] = enc_h[row0 * HH + i];
    for (int i = tid; i < TM * DD; i += NT) ps[i] = last_pos[row0 * DD + i];
    for (int i = tid; i < G4; i += NT) bg[i] = b_ih[i] + b_hh[i];
    if (tid < 256) { wposI[2 * tid] = W_pos[tid]; wposI[2 * tid + 1] = W_pos[HH + tid]; }
    for (int i = tid; i < 128; i += NT) { s_wun2[i] = W_un2[i]; s_wemb[i] = W_embed[i]; }
    if (tid < 64) {
        s_bsp1[tid] = b_sp1[tid]; s_bun1[tid] = b_un1[tid];
        s_wsp2[tid] = W_sp2[tid]; s_bemb[tid] = b_embed[tid];
    }
    if (tid == 0) {
        s_misc[0] = b_pos[0]; s_misc[1] = b_pos[1];
        s_misc[2] = b_sp2[0]; s_misc[3] = b_un2[0]; s_misc[4] = b_un2[1];
    }
    __syncthreads();

    float* out_pred = out;
    float* out_sp   = out + (size_t)BB * PP * 2;
    float* out_un   = out + (size_t)BB * PP * 3;

    // flat copy of one 8192-float tile (gate or head), NT*4 floats/thread x 4
    #define STAGE(t)  do {                                                          \
        const float* src = ((t) < NGT) ? (g_Wt2 + (size_t)(t) * TILE_FLOATS)        \
                                       : (g_WheadT + (size_t)((t) - NGT) * TILE_FLOATS); \
        float* dst = wtb + ((t) & 1) * TILE_FLOATS;                                 \
        _Pragma("unroll")                                                           \
        for (int it_ = 0; it_ < 4; it_++) {                                         \
            int fi_ = (it_ * NT + tid) * 4;                                         \
            *(float4*)&dst[fi_] = *(const float4*)&src[fi_];                        \
        }                                                                           \
    } while (0)

    for (int step = 0; step < PP; step++) {
        float* hsOld = (step & 1) ? hs1 : hs0;
        float* hsNew = (step & 1) ? hs0 : hs1;

        // ---- 1. emb: warp-set 0 only (own 8 rows) ----
        if (ws == 0) {
            for (int i = lane; i < 8 * EE; i += 32) {
                int r = i >> 6, e = i & 63;
                int row = myrow + r;
                float v = fmaf(ps[row * 2], s_wemb[e * 2],
                          fmaf(ps[row * 2 + 1], s_wemb[e * 2 + 1], s_bemb[e]));
                embs[row * EE + e] = fmaxf(v, 0.f);
            }
        }
        STAGE(0);
        __syncthreads();

        // ---- 2. gates: 2 passes; warp handles hc = ws*2+p, 8 rows ----
        #pragma unroll 1
        for (int p = 0; p < 2; p++) {
            const int hc = ws * 2 + p;
            const int jb = hc * 64 + 2 * lane;

            // prefetch c pairs (global scratch; enc_c on step 0)
            float2 cpre[8];
            {
                const float* cbase = (step == 0) ? enc_c : g_c;
                #pragma unroll
                for (int r = 0; r < 8; r++)
                    cpre[r] = *(const float2*)&cbase[(size_t)(row0 + myrow + r) * HH + jb];
            }

            u64 acc2[32];   // [gate 4][row 8]
            #pragma unroll
            for (int i = 0; i < 32; i++) acc2[i] = 0ULL;

            #pragma unroll 1
            for (int ti = 0; ti < 20; ti++) {
                int t = p * 20 + ti;
                if (t + 1 < NTILES) STAGE(t + 1);
                const float* wt = wtb + (t & 1) * TILE_FLOATS;
                int kt = ti * KT;
                const float* Abase = (kt < EE) ? (embs + kt) : (hsOld + (kt - EE));
                const int astr     = (kt < EE) ? EE : HH;

                #pragma unroll
                for (int k2 = 0; k2 < KT; k2 += 2) {
                    float2 a2[8];
                    #pragma unroll
                    for (int r = 0; r < 8; r++)
                        a2[r] = *(const float2*)&Abase[(myrow + r) * astr + k2];
                    #pragma unroll
                    for (int kk = 0; kk < 2; kk++) {
                        const float* wr = &wt[(k2 + kk) * 512 + ws * 256 + 2 * lane];
                        u64 w0 = *(const u64*)&wr[0];
                        u64 w1 = *(const u64*)&wr[64];
                        u64 w2 = *(const u64*)&wr[128];
                        u64 w3 = *(const u64*)&wr[192];
                        #pragma unroll
                        for (int r = 0; r < 8; r++) {
                            float av = kk ? a2[r].y : a2[r].x;
                            u64 av2 = pack2(av, av);
                            FMA2(acc2[r],      av2, w0);
                            FMA2(acc2[8 + r],  av2, w1);
                            FMA2(acc2[16 + r], av2, w2);
                            FMA2(acc2[24 + r], av2, w3);
                        }
                    }
                }
                __syncthreads();
            }

            // cell update for this hc block (writes hsNew own cols + g_c)
            float2 bi  = *(const float2*)&bg[jb];
            float2 bf  = *(const float2*)&bg[256 + jb];
            float2 bgt = *(const float2*)&bg[512 + jb];
            float2 bo  = *(const float2*)&bg[768 + jb];
            #pragma unroll
            for (int r = 0; r < 8; r++) {
                float i0, i1, f0, f1, g0, g1, o0, o1;
                unpack2(acc2[r],      i0, i1);
                unpack2(acc2[8 + r],  f0, f1);
                unpack2(acc2[16 + r], g0, g1);
                unpack2(acc2[24 + r], o0, o1);
                float cn0 = sigf(f0 + bf.x) * cpre[r].x + sigf(i0 + bi.x) * tanhf(g0 + bgt.x);
                float cn1 = sigf(f1 + bf.y) * cpre[r].y + sigf(i1 + bi.y) * tanhf(g1 + bgt.y);
                *(float2*)&g_c[(size_t)(row0 + myrow + r) * HH + jb] = make_float2(cn0, cn1);
                float h0 = sigf(o0 + bo.x) * tanhf(cn0);
                float h1 = sigf(o1 + bo.y) * tanhf(cn1);
                *(float2*)&hsNew[(myrow + r) * HH + jb] = make_float2(h0, h1);
            }
        }
        __syncthreads();   // all hsNew columns written before heads read

        // ---- 3. heads: ws0 = sp1 + pos, ws1 = un1 (8 rows each) ----
        u64 t2[8], p2[8];
        #pragma unroll
        for (int r = 0; r < 8; r++) { t2[r] = 0ULL; p2[r] = 0ULL; }

        #pragma unroll 1
        for (int ht = 0; ht < 4; ht++) {
            int t = NGT + ht;
            if (t + 1 < NTILES) STAGE(t + 1);
            const float* wt = wtb + (t & 1) * TILE_FLOATS;
            int kt = ht * KTH;
            #pragma unroll 4
            for (int k2 = 0; k2 < KTH; k2 += 2) {
                float2 h2[8];
                #pragma unroll
                for (int r = 0; r < 8; r++)
                    h2[r] = *(const float2*)&hsNew[(myrow + r) * HH + kt + k2];
                #pragma unroll
                for (int kk = 0; kk < 2; kk++) {
                    const float* wr = &wt[(k2 + kk) * 128];
                    u64 wh = *(const u64*)&wr[ws * 64 + 2 * lane];
                    u64 wpp = 0ULL;
                    if (ws == 0) wpp = *(const u64*)&wposI[(kt + k2 + kk) * 2];
                    #pragma unroll
                    for (int r = 0; r < 8; r++) {
                        float hv = kk ? h2[r].y : h2[r].x;
                        u64 hv2 = pack2(hv, hv);
                        FMA2(t2[r], hv2, wh);
                        if (ws == 0) FMA2(p2[r], hv2, wpp);
                    }
                }
            }
            __syncthreads();
        }

        // ---- epilogue ----
        if (ws == 0) {
            float bspa = s_bsp1[2 * lane], bspb = s_bsp1[2 * lane + 1];
            float wspa = s_wsp2[2 * lane], wspb = s_wsp2[2 * lane + 1];
            #pragma unroll
            for (int r = 0; r < 8; r++) {
                float ta, tb, pr0, pr1;
                unpack2(t2[r], ta, tb);
                unpack2(p2[r], pr0, pr1);
                ta = fmaxf(ta + bspa, 0.f); tb = fmaxf(tb + bspb, 0.f);
                float spv = ta * wspa + tb * wspb;
                #pragma unroll
                for (int off = 16; off > 0; off >>= 1)
                    spv += __shfl_xor_sync(0xffffffffu, spv, off);
                if (lane == 0) {
                    int row = myrow + r;
                    int b   = row0 + row;
                    float p0 = ps[row * 2]     + pr0 + s_misc[0];
                    float p1 = ps[row * 2 + 1] + pr1 + s_misc[1];
                    size_t base = (size_t)b * PP + step;
                    out_pred[base * 2]     = p0;
                    out_pred[base * 2 + 1] = p1;
                    out_sp[base]           = softplusf(spv + s_misc[2]);
                    ps[row * 2] = p0; ps[row * 2 + 1] = p1;
                }
            }
        } else {
            float buna = s_bun1[2 * lane], bunb = s_bun1[2 * lane + 1];
            float wu0a = s_wun2[2 * lane],      wu0b = s_wun2[2 * lane + 1];
            float wu1a = s_wun2[64 + 2 * lane], wu1b = s_wun2[64 + 2 * lane + 1];
            #pragma unroll
            for (int r = 0; r < 8; r++) {
                float ua, ub;
                unpack2(t2[r], ua, ub);
                ua = fmaxf(ua + buna, 0.f); ub = fmaxf(ub + bunb, 0.f);
                float un0 = ua * wu0a + ub * wu0b;
                float un1 = ua * wu1a + ub * wu1b;
                #pragma unroll
                for (int off = 16; off > 0; off >>= 1) {
                    un0 += __shfl_xor_sync(0xffffffffu, un0, off);
                    un1 += __shfl_xor_sync(0xffffffffu, un1, off);
                }
                if (lane == 0) {
                    size_t base = (size_t)(row0 + myrow + r) * PP + step;
                    out_un[base * 2]     = expf(un0 + s_misc[3]);
                    out_un[base * 2 + 1] = expf(un1 + s_misc[4]);
                }
            }
        }
        __syncwarp();   // ps writes visible within ws0 warps before next emb
    }
    #undef STAGE
}

extern "C" void kernel_launch(void* const* d_in, const int* in_sizes, int n_in,
                              void* d_out, int out_size) {
    (void)in_sizes; (void)n_in; (void)out_size;
    const float* enc_h    = (const float*)d_in[0];
    const float* enc_c    = (const float*)d_in[1];
    const float* last_pos = (const float*)d_in[2];
    const float* W_embed  = (const float*)d_in[3];
    const float* b_embed  = (const float*)d_in[4];
    const float* W_ih     = (const float*)d_in[5];
    const float* W_hh     = (const float*)d_in[6];
    const float* b_ih     = (const float*)d_in[7];
    const float* b_hh     = (const float*)d_in[8];
    const float* W_pos    = (const float*)d_in[9];
    const float* b_pos    = (const float*)d_in[10];
    const float* W_sp1    = (const float*)d_in[11];
    const float* b_sp1    = (const float*)d_in[12];
    const float* W_sp2    = (const float*)d_in[13];
    const float* b_sp2    = (const float*)d_in[14];
    const float* W_un1    = (const float*)d_in[15];
    const float* b_un1    = (const float*)d_in[16];
    const float* W_un2    = (const float*)d_in[17];
    const float* b_un2    = (const float*)d_in[18];

    int prep_total = NGT * TILE_FLOATS + HH * 128;
    prep_kernel<<<(prep_total + 255) / 256, 256>>>(W_ih, W_hh, W_sp1, W_un1);

    const size_t smem = SMEM_FLOATS * sizeof(float);   // ~216.5 KB
    cudaFuncSetAttribute(lstm_kernel, cudaFuncAttributeMaxDynamicSharedMemorySize, (int)smem);
    lstm_kernel<<<BB / TM, NT, smem>>>(enc_h, enc_c, last_pos, W_embed, b_embed,
                                       b_ih, b_hh, W_pos, b_pos, b_sp1, W_sp2, b_sp2,
                                       b_un1, W_un2, b_un2, (float*)d_out);
}

// round 16
// speedup vs baseline: 1.0205x; 1.0205x over previous
#include <cuda_runtime.h>
#include <math.h>

#define BB 65536
#define HH 256
#define EE 64
#define DD 2
#define PP 12
#define G4 1024
#define KTOT 320
#define TM 64            // rows per CTA
#define NT 512           // 16 warps: 2 warp-sets x 8 row-groups, 8 rows/warp
#define KT 16            // gate k-tile
#define KTH 64           // head k-tile
#define NGT 40           // gate tiles: 2 passes x 20
#define NTILES 44        // + 4 head tiles
#define TILE_FLOATS 8192
#define SMEM_FLOATS 55432

typedef unsigned long long u64;

// -------- scratch (allocation-free: __device__ globals) --------
__device__ float g_Wt2[NGT * TILE_FLOATS];     // gate weights, tile-ordered
__device__ float g_WheadT[HH * 128];           // [k][0..63]=W_sp1^T, [64..127]=W_un1^T
__device__ float g_c[(size_t)BB * HH];         // c-state scratch (64 MB)

__global__ void prep_kernel(const float* __restrict__ W_ih,
                            const float* __restrict__ W_hh,
                            const float* __restrict__ W_sp1,
                            const float* __restrict__ W_un1) {
    int idx = blockIdx.x * blockDim.x + threadIdx.x;
    const int gate_total = NGT * TILE_FLOATS;
    if (idx < gate_total) {
        int col  = idx & 511;
        int rest = idx >> 9;
        int k    = rest & 15;
        int tile = rest >> 4;           // 0..39
        int p = tile / 20, ti = tile % 20;
        int ws = col >> 8;
        int within = col & 255;
        int g  = within >> 6;
        int jj = within & 63;
        int kk = ti * KT + k;
        int jrow = g * 256 + (ws * 2 + p) * 64 + jj;
        g_Wt2[idx] = (kk < EE) ? W_ih[jrow * EE + kk] : W_hh[jrow * HH + (kk - EE)];
    } else {
        int r = idx - gate_total;
        if (r < HH * 128) {
            int k = r >> 7, o = r & 127;
            g_WheadT[r] = (o < 64) ? W_sp1[o * HH + k] : W_un1[(o - 64) * HH + k];
        }
    }
}

__device__ __forceinline__ float softplusf(float x) {
    return fmaxf(x, 0.f) + log1pf(expf(-fabsf(x)));
}
__device__ __forceinline__ u64 pack2(float lo, float hi) {
    u64 r;
    asm("mov.b64 %0, {%1, %2};" : "=l"(r)
        : "r"(__float_as_uint(lo)), "r"(__float_as_uint(hi)));
    return r;
}
__device__ __forceinline__ void unpack2(u64 v, float& lo, float& hi) {
    unsigned int a, b;
    asm("mov.b64 {%0, %1}, %2;" : "=r"(a), "=r"(b) : "l"(v));
    lo = __uint_as_float(a); hi = __uint_as_float(b);
}
#define FMA2(d, a, b) asm("fma.rn.f32x2 %0, %1, %2, %0;" : "+l"(d) : "l"(a), "l"(b))

// ---- packed f32x2 arithmetic (FMA pipe; no MUFU) ----
__device__ __forceinline__ u64 f2_add(u64 a, u64 b) {
    u64 d; asm("add.rn.f32x2 %0, %1, %2;" : "=l"(d) : "l"(a), "l"(b)); return d;
}
__device__ __forceinline__ u64 f2_mul(u64 a, u64 b) {
    u64 d; asm("mul.rn.f32x2 %0, %1, %2;" : "=l"(d) : "l"(a), "l"(b)); return d;
}
__device__ __forceinline__ u64 f2_fma(u64 a, u64 b, u64 c) {
    u64 d; asm("fma.rn.f32x2 %0, %1, %2, %3;" : "=l"(d) : "l"(a), "l"(b), "l"(c)); return d;
}
__device__ __forceinline__ u64 dup2(float v) { return pack2(v, v); }
__device__ __forceinline__ void ubits(u64 v, unsigned& a, unsigned& b) {
    asm("mov.b64 {%0, %1}, %2;" : "=r"(a), "=r"(b) : "l"(v));
}
__device__ __forceinline__ u64 pbits(unsigned a, unsigned b) {
    u64 r; asm("mov.b64 %0, {%1, %2};" : "=l"(r) : "r"(a), "r"(b)); return r;
}
// build 2^n float bits from magic-rint bits u = bits(t + 12582912), clamped
__device__ __forceinline__ unsigned sclamp(unsigned u) {
    int k = (int)(u - 0x4B3FFF81u);           // n + 127
    k = k < 1 ? 1 : (k > 253 ? 253 : k);
    return ((unsigned)k) << 23;
}
// packed sigmoid: 1/(1+2^(-x*log2e)); exp2 = rint split + deg-5 poly; recip = magic + 3 Newton
__device__ __forceinline__ u64 sig2(u64 x2) {
    u64 t2 = f2_mul(x2, dup2(-1.4426950408889634f));
    u64 u2 = f2_add(t2, dup2(12582912.0f));
    u64 n2 = f2_add(u2, dup2(-12582912.0f));
    u64 r2 = f2_fma(n2, dup2(-1.0f), t2);             // r = t - rint(t), in [-0.5,0.5]
    unsigned ua, ub; ubits(u2, ua, ub);
    u64 s2 = pbits(sclamp(ua), sclamp(ub));           // 2^n
    u64 p  = dup2(1.33335581e-3f);
    p = f2_fma(p, r2, dup2(9.61812910e-3f));
    p = f2_fma(p, r2, dup2(5.55041087e-2f));
    p = f2_fma(p, r2, dup2(2.40226507e-1f));
    p = f2_fma(p, r2, dup2(6.93147181e-1f));
    p = f2_fma(p, r2, dup2(1.0f));                    // 2^r
    u64 y2 = f2_fma(p, s2, dup2(1.0f));               // 1 + 2^t
    unsigned ya, yb; ubits(y2, ya, yb);
    u64 rr = pbits(0x7EF311C3u - ya, 0x7EF311C3u - yb);
    u64 ny = f2_mul(y2, dup2(-1.0f));
    u64 TWO = dup2(2.0f);
    rr = f2_mul(rr, f2_fma(ny, rr, TWO));
    rr = f2_mul(rr, f2_fma(ny, rr, TWO));
    rr = f2_mul(rr, f2_fma(ny, rr, TWO));
    return rr;
}
__device__ __forceinline__ u64 tanh2(u64 x2) {        // tanh = 2*sigmoid(2x) - 1
    u64 s = sig2(f2_add(x2, x2));
    return f2_fma(s, dup2(2.0f), dup2(-1.0f));
}

// -------- main persistent-state kernel --------
__global__ void __launch_bounds__(NT, 1)
lstm_kernel(const float* __restrict__ enc_h, const float* __restrict__ enc_c,
            const float* __restrict__ last_pos,
            const float* __restrict__ W_embed, const float* __restrict__ b_embed,
            const float* __restrict__ b_ih, const float* __restrict__ b_hh,
            const float* __restrict__ W_pos, const float* __restrict__ b_pos,
            const float* __restrict__ b_sp1, const float* __restrict__ W_sp2,
            const float* __restrict__ b_sp2,
            const float* __restrict__ b_un1, const float* __restrict__ W_un2,
            const float* __restrict__ b_un2,
            float* __restrict__ out)
{
    extern __shared__ float sm[];
    float* hs0   = sm;                    // 16384
    float* hs1   = hs0 + TM * HH;         // 16384
    float* embs  = hs1 + TM * HH;         // 4096
    float* wtb   = embs + TM * EE;        // 2 x 8192
    float* bg    = wtb + 2 * TILE_FLOATS; // 1024
    float* wposI = bg + G4;               // 512: [k][2] interleaved
    float* s_bsp1 = wposI + 512;          // 64
    float* s_bun1 = s_bsp1 + 64;          // 64
    float* s_wsp2 = s_bun1 + 64;          // 64
    float* s_wun2 = s_wsp2 + 64;          // 128
    float* s_wemb = s_wun2 + 128;         // 128
    float* s_bemb = s_wemb + 128;         // 64
    float* s_misc = s_bemb + 64;          // 8
    float* ps     = s_misc + 8;           // 128   total 55432

    const int tid  = threadIdx.x;
    const int lane = tid & 31;
    const int w    = tid >> 5;            // 0..15
    const int ws   = w >> 3;              // warp-set 0/1 (j-split)
    const int wg   = w & 7;               // row-group
    const int myrow = wg * 8;             // warp owns 8 rows
    const int row0 = blockIdx.x * TM;

    // ---- init ----
    for (int i = tid; i < TM * HH; i += NT) hs0[i] = enc_h[row0 * HH + i];
    for (int i = tid; i < TM * DD; i += NT) ps[i] = last_pos[row0 * DD + i];
    for (int i = tid; i < G4; i += NT) bg[i] = b_ih[i] + b_hh[i];
    if (tid < 256) { wposI[2 * tid] = W_pos[tid]; wposI[2 * tid + 1] = W_pos[HH + tid]; }
    for (int i = tid; i < 128; i += NT) { s_wun2[i] = W_un2[i]; s_wemb[i] = W_embed[i]; }
    if (tid < 64) {
        s_bsp1[tid] = b_sp1[tid]; s_bun1[tid] = b_un1[tid];
        s_wsp2[tid] = W_sp2[tid]; s_bemb[tid] = b_embed[tid];
    }
    if (tid == 0) {
        s_misc[0] = b_pos[0]; s_misc[1] = b_pos[1];
        s_misc[2] = b_sp2[0]; s_misc[3] = b_un2[0]; s_misc[4] = b_un2[1];
    }
    __syncthreads();

    float* out_pred = out;
    float* out_sp   = out + (size_t)BB * PP * 2;
    float* out_un   = out + (size_t)BB * PP * 3;

    // flat copy of one 8192-float tile (gate or head)
    #define STAGE(t)  do {                                                          \
        const float* src = ((t) < NGT) ? (g_Wt2 + (size_t)(t) * TILE_FLOATS)        \
                                       : (g_WheadT + (size_t)((t) - NGT) * TILE_FLOATS); \
        float* dst = wtb + ((t) & 1) * TILE_FLOATS;                                 \
        _Pragma("unroll")                                                           \
        for (int it_ = 0; it_ < 4; it_++) {                                         \
            int fi_ = (it_ * NT + tid) * 4;                                         \
            *(float4*)&dst[fi_] = *(const float4*)&src[fi_];                        \
        }                                                                           \
    } while (0)

    for (int step = 0; step < PP; step++) {
        float* hsOld = (step & 1) ? hs1 : hs0;
        float* hsNew = (step & 1) ? hs0 : hs1;

        // ---- 1. emb: warp-set 0 only (own 8 rows) ----
        if (ws == 0) {
            for (int i = lane; i < 8 * EE; i += 32) {
                int r = i >> 6, e = i & 63;
                int row = myrow + r;
                float v = fmaf(ps[row * 2], s_wemb[e * 2],
                          fmaf(ps[row * 2 + 1], s_wemb[e * 2 + 1], s_bemb[e]));
                embs[row * EE + e] = fmaxf(v, 0.f);
            }
        }
        STAGE(0);
        __syncthreads();

        // ---- 2. gates: 2 passes; warp handles hc = ws*2+p, 8 rows ----
        #pragma unroll 1
        for (int p = 0; p < 2; p++) {
            const int hc = ws * 2 + p;
            const int jb = hc * 64 + 2 * lane;

            // prefetch c pairs (global scratch; enc_c on step 0)
            u64 cpre2[8];
            {
                const float* cbase = (step == 0) ? enc_c : g_c;
                #pragma unroll
                for (int r = 0; r < 8; r++)
                    cpre2[r] = *(const u64*)&cbase[(size_t)(row0 + myrow + r) * HH + jb];
            }

            u64 acc2[32];   // [gate 4][row 8]
            #pragma unroll
            for (int i = 0; i < 32; i++) acc2[i] = 0ULL;

            #pragma unroll 1
            for (int ti = 0; ti < 20; ti++) {
                int t = p * 20 + ti;
                if (t + 1 < NTILES) STAGE(t + 1);
                const float* wt = wtb + (t & 1) * TILE_FLOATS;
                int kt = ti * KT;
                const float* Abase = (kt < EE) ? (embs + kt) : (hsOld + (kt - EE));
                const int astr     = (kt < EE) ? EE : HH;

                #pragma unroll
                for (int k2 = 0; k2 < KT; k2 += 2) {
                    float2 a2[8];
                    #pragma unroll
                    for (int r = 0; r < 8; r++)
                        a2[r] = *(const float2*)&Abase[(myrow + r) * astr + k2];
                    #pragma unroll
                    for (int kk = 0; kk < 2; kk++) {
                        const float* wr = &wt[(k2 + kk) * 512 + ws * 256 + 2 * lane];
                        u64 w0 = *(const u64*)&wr[0];
                        u64 w1 = *(const u64*)&wr[64];
                        u64 w2 = *(const u64*)&wr[128];
                        u64 w3 = *(const u64*)&wr[192];
                        #pragma unroll
                        for (int r = 0; r < 8; r++) {
                            float av = kk ? a2[r].y : a2[r].x;
                            u64 av2 = pack2(av, av);
                            FMA2(acc2[r],      av2, w0);
                            FMA2(acc2[8 + r],  av2, w1);
                            FMA2(acc2[16 + r], av2, w2);
                            FMA2(acc2[24 + r], av2, w3);
                        }
                    }
                }
                __syncthreads();
            }

            // cell update for this hc block — packed, MUFU-free
            u64 bi2 = *(const u64*)&bg[jb];
            u64 bf2 = *(const u64*)&bg[256 + jb];
            u64 bG2 = *(const u64*)&bg[512 + jb];
            u64 bo2 = *(const u64*)&bg[768 + jb];
            #pragma unroll
            for (int r = 0; r < 8; r++) {
                u64 xi = f2_add(acc2[r],      bi2);
                u64 xf = f2_add(acc2[8 + r],  bf2);
                u64 xg = f2_add(acc2[16 + r], bG2);
                u64 xo = f2_add(acc2[24 + r], bo2);
                u64 cn = f2_add(f2_mul(sig2(xf), cpre2[r]),
                                f2_mul(sig2(xi), tanh2(xg)));
                *(u64*)&g_c[(size_t)(row0 + myrow + r) * HH + jb] = cn;
                u64 hn = f2_mul(sig2(xo), tanh2(cn));
                *(u64*)&hsNew[(myrow + r) * HH + jb] = hn;
            }
        }
        __syncthreads();   // all hsNew columns written before heads read

        // ---- 3. heads: ws0 = sp1 + pos, ws1 = un1 (8 rows each) ----
        u64 t2[8], p2[8];
        #pragma unroll
        for (int r = 0; r < 8; r++) { t2[r] = 0ULL; p2[r] = 0ULL; }

        #pragma unroll 1
        for (int ht = 0; ht < 4; ht++) {
            int t = NGT + ht;
            if (t + 1 < NTILES) STAGE(t + 1);
            const float* wt = wtb + (t & 1) * TILE_FLOATS;
            int kt = ht * KTH;
            #pragma unroll 4
            for (int k2 = 0; k2 < KTH; k2 += 2) {
                float2 h2[8];
                #pragma unroll
                for (int r = 0; r < 8; r++)
                    h2[r] = *(const float2*)&hsNew[(myrow + r) * HH + kt + k2];
                #pragma unroll
                for (int kk = 0; kk < 2; kk++) {
                    const float* wr = &wt[(k2 + kk) * 128];
                    u64 wh = *(const u64*)&wr[ws * 64 + 2 * lane];
                    u64 wpp = 0ULL;
                    if (ws == 0) wpp = *(const u64*)&wposI[(kt + k2 + kk) * 2];
                    #pragma unroll
                    for (int r = 0; r < 8; r++) {
                        float hv = kk ? h2[r].y : h2[r].x;
                        u64 hv2 = pack2(hv, hv);
                        FMA2(t2[r], hv2, wh);
                        if (ws == 0) FMA2(p2[r], hv2, wpp);
                    }
                }
            }
            __syncthreads();
        }

        // ---- epilogue ----
        if (ws == 0) {
            float bspa = s_bsp1[2 * lane], bspb = s_bsp1[2 * lane + 1];
            float wspa = s_wsp2[2 * lane], wspb = s_wsp2[2 * lane + 1];
            #pragma unroll
            for (int r = 0; r < 8; r++) {
                float ta, tb, pr0, pr1;
                unpack2(t2[r], ta, tb);
                unpack2(p2[r], pr0, pr1);
                ta = fmaxf(ta + bspa, 0.f); tb = fmaxf(tb + bspb, 0.f);
                float spv = ta * wspa + tb * wspb;
                #pragma unroll
                for (int off = 16; off > 0; off >>= 1)
                    spv += __shfl_xor_sync(0xffffffffu, spv, off);
                if (lane == 0) {
                    int row = myrow + r;
                    int b   = row0 + row;
                    float p0 = ps[row * 2]     + pr0 + s_misc[0];
                    float p1 = ps[row * 2 + 1] + pr1 + s_misc[1];
                    size_t base = (size_t)b * PP + step;
                    out_pred[base * 2]     = p0;
                    out_pred[base * 2 + 1] = p1;
                    out_sp[base]           = softplusf(spv + s_misc[2]);
                    ps[row * 2] = p0; ps[row * 2 + 1] = p1;
                }
            }
        } else {
            float buna = s_bun1[2 * lane], bunb = s_bun1[2 * lane + 1];
            float wu0a = s_wun2[2 * lane],      wu0b = s_wun2[2 * lane + 1];
            float wu1a = s_wun2[64 + 2 * lane], wu1b = s_wun2[64 + 2 * lane + 1];
            #pragma unroll
            for (int r = 0; r < 8; r++) {
                float ua, ub;
                unpack2(t2[r], ua, ub);
                ua = fmaxf(ua + buna, 0.f); ub = fmaxf(ub + bunb, 0.f);
                float un0 = ua * wu0a + ub * wu0b;
                float un1 = ua * wu1a + ub * wu1b;
                #pragma unroll
                for (int off = 16; off > 0; off >>= 1) {
                    un0 += __shfl_xor_sync(0xffffffffu, un0, off);
                    un1 += __shfl_xor_sync(0xffffffffu, un1, off);
                }
                if (lane == 0) {
                    size_t base = (size_t)(row0 + myrow + r) * PP + step;
                    out_un[base * 2]     = expf(un0 + s_misc[3]);
                    out_un[base * 2 + 1] = expf(un1 + s_misc[4]);
                }
            }
        }
        __syncwarp();   // ps writes visible within ws0 warps before next emb
    }
    #undef STAGE
}

extern "C" void kernel_launch(void* const* d_in, const int* in_sizes, int n_in,
                              void* d_out, int out_size) {
    (void)in_sizes; (void)n_in; (void)out_size;
    const float* enc_h    = (const float*)d_in[0];
    const float* enc_c    = (const float*)d_in[1];
    const float* last_pos = (const float*)d_in[2];
    const float* W_embed  = (const float*)d_in[3];
    const float* b_embed  = (const float*)d_in[4];
    const float* W_ih     = (const float*)d_in[5];
    const float* W_hh     = (const float*)d_in[6];
    const float* b_ih     = (const float*)d_in[7];
    const float* b_hh     = (const float*)d_in[8];
    const float* W_pos    = (const float*)d_in[9];
    const float* b_pos    = (const float*)d_in[10];
    const float* W_sp1    = (const float*)d_in[11];
    const float* b_sp1    = (const float*)d_in[12];
    const float* W_sp2    = (const float*)d_in[13];
    const float* b_sp2    = (const float*)d_in[14];
    const float* W_un1    = (const float*)d_in[15];
    const float* b_un1    = (const float*)d_in[16];
    const float* W_un2    = (const float*)d_in[17];
    const float* b_un2    = (const float*)d_in[18];

    int prep_total = NGT * TILE_FLOATS + HH * 128;
    prep_kernel<<<(prep_total + 255) / 256, 256>>>(W_ih, W_hh, W_sp1, W_un1);

    const size_t smem = SMEM_FLOATS * sizeof(float);   // ~216.5 KB
    cudaFuncSetAttribute(lstm_kernel, cudaFuncAttributeMaxDynamicSharedMemorySize, (int)smem);
    lstm_kernel<<<BB / TM, NT, smem>>>(enc_h, enc_c, last_pos, W_embed, b_embed,
                                       b_ih, b_hh, W_pos, b_pos, b_sp1, W_sp2, b_sp2,
                                       b_un1, W_un2, b_un2, (float*)d_out);
}